// round 15
// baseline (speedup 1.0000x reference)
#include <cuda_runtime.h>
#include <cstdint>

// Problem constants (fixed by the reference: B=8, N=16384, RATIO=0.5, C=128)
#define BB 8
#define NN 16384
#define NPOINT 8192
#define CC 128
#define T 128                // threads per CTA (4 warps) — best measured (R10)
#define CSIZE 8              // CTAs per batch — 16 regressed 3.5x (R7)
#define NC (NN / CSIZE)      // 2048 points per CTA
#define NWARP (T / 32)       // 4 warps
#define PPT (NC / T)         // 16 points per thread
#define NSLOT (CSIZE * NWARP)  // 32 cross slots per buffer (one per lane)
#define CW (CSIZE * NWARP)     // 32 warps per cluster — gather rotation period

typedef unsigned long long u64;
typedef unsigned int u32;

// ---------------------------------------------------------------------------
// helpers
// ---------------------------------------------------------------------------
__device__ __forceinline__ u32 smem_u32(const void* p) {
    return (u32)__cvta_generic_to_shared(p);
}
__device__ __forceinline__ u64 vld64(u32 a) {
    u64 v;
    asm volatile("ld.volatile.shared.b64 %0, [%1];" : "=l"(v) : "r"(a) : "memory");
    return v;
}
__device__ __forceinline__ u32 mapa_rank(u32 laddr, u32 rank) {
    u32 ra;
    asm volatile("mapa.shared::cluster.u32 %0, %1, %2;" : "=r"(ra) : "r"(laddr), "r"(rank));
    return ra;
}
__device__ __forceinline__ void st_cluster64(u32 raddr, u64 v) {
    asm volatile("st.relaxed.cluster.shared::cluster.b64 [%0], %1;" :: "r"(raddr), "l"(v) : "memory");
}

// ---------------------------------------------------------------------------
// FPS + fused gather: 8-CTA cluster per batch, 128 threads/CTA, 16 pts/thread.
// FPS core (compute / argmax tree / REDUX / all-to-all / voted poll) is
// BYTE-IDENTICAL in logic to the best kernel (R10/R12/R14, 2497-2508us).
// Known-regressing variants (do not revisit): CSIZE=16 (R7, 3.5x), divergent
// spin (R8, 3x), hand-packed f32x2 math (R2 wrong / R11 +8%).
//
// R15: both output gathers are fused into the ~215-cyc DSMEM dead window
// (between posting the warp key and the slot data arriving):
//   feats: iteration j handled by rotating warp W=j%32 (4 c's per lane),
//          software-pipelined — at its turn a warp STOREs the 4 values it
//          LOADed 32 iterations ago (latency long covered), then issues the
//          4 loads for the current f. ~60 cyc of issue inside the window,
//          one warp per cluster per iteration => ~0 critical-path cost.
//   xyz:   rank0/tid0 writes (cx,cy,cz) — already in registers, bit-exact
//          smem copies of xyz[b][f].
// This removes the separate 31us gather kernel and g_idx entirely.
//
// Per-point distance arithmetic is the VERBATIM scalar expression from the
// rel_err==0.0 kernels — do not touch.
// ---------------------------------------------------------------------------
extern "C" __global__ void __launch_bounds__(T, 1) __cluster_dims__(CSIZE, 1, 1)
fps_kernel(const float* __restrict__ xyz,
           const float* __restrict__ feats,
           float* __restrict__ out_feats,
           float* __restrict__ out_xyz)
{
    const int blk  = blockIdx.x;
    const int b    = blk / CSIZE;
    const u32 rank = (u32)(blk % CSIZE);
    const int tid  = threadIdx.x;
    const int wid  = tid >> 5;
    const int lane = tid & 31;

    extern __shared__ float smem[];
    float2* sxy = (float2*)smem;                    // [NN]  (128 KB)
    float*  sz  = smem + 2 * NN;                    // [NN]  (64 KB)
    u64* crossSlots = (u64*)(smem + 3 * NN);        // [2][NSLOT]

    const float* __restrict__ p = xyz + (size_t)b * NN * 3;

    // Full xyz table in smem (centroid lookup must cover all 16384 points)
    for (int i = tid; i < NN; i += T) {
        float x = p[3 * i + 0];
        float y = p[3 * i + 1];
        float z = p[3 * i + 2];
        sxy[i] = make_float2(x, y);
        sz[i]  = z;
    }
    if (tid < 2 * NSLOT) crossSlots[tid] = 0ull;
    __syncthreads();
    // all CTAs' slots must be zeroed before any peer's first DSMEM store
    asm volatile("barrier.cluster.arrive.aligned;" ::: "memory");
    asm volatile("barrier.cluster.wait.aligned;"   ::: "memory");

    // Own 16 points, register-resident: i_k = base + k*T (k asc => index asc)
    const int base = (int)rank * NC + tid;
    float X[PPT], Y[PPT], Z[PPT], D[PPT];
#pragma unroll
    for (int k = 0; k < PPT; k++) {
        const int i = base + k * T;
        float2 xy = sxy[i];
        X[k] = xy.x; Y[k] = xy.y; Z[k] = sz[i];
        D[k] = 1e10f;
    }

    const u32 csBase = smem_u32(crossSlots);

    // Per-lane peer address: lanes 0..7 target rank=lane, slot [rank*NWARP+wid].
    const u32 peerAddr = mapa_rank(csBase, (u32)(lane & (CSIZE - 1)))
                       + (u32)(((int)rank * NWARP + wid) * 8);

    // Lane L polls slot L (32 slots <-> 32 lanes).
    const u32 pollAddr = csBase + (u32)(lane * 8);

    // Fused feats gather state: this warp's cluster-wide warp id and its
    // 4 channels (c = lane + 32q). Pending values loaded at the previous
    // turn, stored at the next turn (32-iteration pipeline).
    const int W = (int)rank * NWARP + wid;          // 0..31
    const float* __restrict__ frow = feats + ((size_t)b * CC + lane) * NN;
    float* __restrict__ orow = out_feats + ((size_t)b * CC + lane) * NPOINT;
    float pend0, pend1, pend2, pend3;
    int m_pend = -1;
    float* __restrict__ oxyz = out_xyz + (size_t)b * NPOINT * 3;

    int f = 0;   // init_far = 0 (reference)

    for (int j = 0; j < NPOINT; j++) {
        const u32 tag = (u32)(j + 1);   // 1..8192 (14 bits)
        const u32 bufOff = (u32)((j & 1) * (NSLOT * 8));

        // distance update — IDENTICAL source expression to prior passing rounds
        const float2 cxy = sxy[f];
        const float cz = sz[f];
        const float cx = cxy.x, cy = cxy.y;
        float nd[PPT];
#pragma unroll
        for (int k = 0; k < PPT; k++) {
            float dx = X[k] - cx;
            float dy = Y[k] - cy;
            float dz = Z[k] - cz;
            float d = dx * dx + dy * dy + dz * dz;
            float v = fminf(D[k], d);
            D[k] = v;
            nd[k] = v;
        }

        // thread-level argmax tree over 16 values; prefer-left keeps lowest k
        // (k ascending == global index ascending): first-index tie-break.
        float bd[PPT]; int bk[PPT];
#pragma unroll
        for (int k = 0; k < PPT; k++) { bd[k] = nd[k]; bk[k] = k; }
#pragma unroll
        for (int s = PPT / 2; s > 0; s >>= 1) {
#pragma unroll
            for (int k = 0; k < PPT; k++) {
                if (k < s) {
                    if (bd[k + s] > bd[k]) { bd[k] = bd[k + s]; bk[k] = bk[k + s]; }
                }
            }
        }
        const float best = bd[0];
        const int   bi   = base + bk[0] * T;

        // warp-level: max dist bits, then max of (NN-1-idx) among maxima
        const u32 ub  = __float_as_uint(best);          // dist >= 0: bit order == float order
        const u32 wm  = __reduce_max_sync(0xFFFFFFFFu, ub);
        const u32 cnd = (ub == wm) ? (u32)(NN - 1 - bi) : 0u;
        const u32 wi  = __reduce_max_sync(0xFFFFFFFFu, cnd);

        // all-to-all: lanes 0..7 each fire ONE remote store (parallel fan-out)
        const u64 wkey = ((u64)wm << 32) | ((u64)tag << 16) | (u64)wi;
        if (lane < CSIZE)
            st_cluster64(peerAddr + bufOff, wkey);

        // ---- fused gather inside the DSMEM dead window ----
        // xyz output for m=j: (cx,cy,cz) are bit-exact copies of xyz[b][f].
        if (rank == 0 && tid == 0) {
            oxyz[j * 3 + 0] = cx;
            oxyz[j * 3 + 1] = cy;
            oxyz[j * 3 + 2] = cz;
        }
        // feats output: rotating warp; store pending (loaded 32 iters ago),
        // then load this iteration's 4 channel values at index f.
        if ((j & (CW - 1)) == W) {
            if (m_pend >= 0) {
                orow[0 * 32 * NPOINT + m_pend] = pend0;
                orow[1 * 32 * NPOINT + m_pend] = pend1;
                orow[2 * 32 * NPOINT + m_pend] = pend2;
                orow[3 * 32 * NPOINT + m_pend] = pend3;
            }
            pend0 = frow[0 * 32 * NN + f];
            pend1 = frow[1 * 32 * NN + f];
            pend2 = frow[2 * 32 * NN + f];
            pend3 = frow[3 * 32 * NN + f];
            m_pend = j;
        }

        // every warp: CONVERGENT voted poll, one slot per lane
        u64 k;
        do {
            k = vld64(pollAddr + bufOff);
        } while (__any_sync(0xFFFFFFFFu, (((u32)k >> 16) ^ tag) != 0u));

        const u32 hi = (u32)(k >> 32);
        const u32 lo = (u32)k;
        const u32 M1 = __reduce_max_sync(0xFFFFFFFFu, hi);
        const u32 C1 = (hi == M1) ? lo : 0u;  // tag bits identical across lanes
        const u32 M2 = __reduce_max_sync(0xFFFFFFFFu, C1);
        f = NN - 1 - (int)(M2 & 0x3FFFu);
    }

    // flush the last pending feats chunk (each warp's final turn)
    if (m_pend >= 0) {
        orow[0 * 32 * NPOINT + m_pend] = pend0;
        orow[1 * 32 * NPOINT + m_pend] = pend1;
        orow[2 * 32 * NPOINT + m_pend] = pend2;
        orow[3 * 32 * NPOINT + m_pend] = pend3;
    }
}

// ---------------------------------------------------------------------------
extern "C" void kernel_launch(void* const* d_in, const int* in_sizes, int n_in,
                              void* d_out, int out_size) {
    // Identify inputs by element count (robust to ordering):
    // feats = 8*128*16384 = 16777216, xyz = 8*16384*3 = 393216
    const float* feats = (const float*)d_in[0];
    const float* xyz   = (const float*)d_in[1];
    if (in_sizes[0] == BB * NN * 3) {
        xyz   = (const float*)d_in[0];
        feats = (const float*)d_in[1];
    }

    float* out = (float*)d_out;
    float* out_feats = out;                                   // B*C*NPOINT
    float* out_xyz   = out + (size_t)BB * CC * NPOINT;        // B*NPOINT*3

    const size_t smem = (size_t)3 * NN * sizeof(float)
                      + 2 * NSLOT * sizeof(u64);
    cudaFuncSetAttribute(fps_kernel,
                         cudaFuncAttributeMaxDynamicSharedMemorySize,
                         (int)smem);

    fps_kernel<<<BB * CSIZE, T, smem>>>(xyz, feats, out_feats, out_xyz);
}

// round 16
// speedup vs baseline: 1.2150x; 1.2150x over previous
#include <cuda_runtime.h>
#include <cstdint>

// Problem constants (fixed by the reference: B=8, N=16384, RATIO=0.5, C=128)
#define BB 8
#define NN 16384
#define NPOINT 8192
#define CC 128
#define T 128                // threads per CTA (4 warps) — best measured (R10)
#define CSIZE 8              // CTAs per batch — 16 regressed 3.5x (R7)
#define NC (NN / CSIZE)      // 2048 points per CTA
#define NWARP (T / 32)       // 4 warps
#define PPT (NC / T)         // 16 points per thread
#define NSLOT (CSIZE * NWARP)  // 32 cross slots per buffer (one per lane)

#define GT 1024              // gather threads per block
#define HCC (CC / 2)         // 64 row-pairs per batch

typedef unsigned long long u64;
typedef unsigned int u32;

// Scratch: selected indices per batch (device global — no allocation allowed)
__device__ int g_idx[BB * NPOINT];

// ---------------------------------------------------------------------------
// helpers
// ---------------------------------------------------------------------------
__device__ __forceinline__ u32 smem_u32(const void* p) {
    return (u32)__cvta_generic_to_shared(p);
}
__device__ __forceinline__ u64 vld64(u32 a) {
    u64 v;
    asm volatile("ld.volatile.shared.b64 %0, [%1];" : "=l"(v) : "r"(a) : "memory");
    return v;
}
__device__ __forceinline__ u32 mapa_rank(u32 laddr, u32 rank) {
    u32 ra;
    asm volatile("mapa.shared::cluster.u32 %0, %1, %2;" : "=r"(ra) : "r"(laddr), "r"(rank));
    return ra;
}
__device__ __forceinline__ void st_cluster64(u32 raddr, u64 v) {
    asm volatile("st.relaxed.cluster.shared::cluster.b64 [%0], %1;" :: "r"(raddr), "l"(v) : "memory");
}

// ---------------------------------------------------------------------------
// FPS: 8-CTA cluster per batch, 128 threads/CTA (4 warps), 16 points/thread
// (register-resident). BYTE-IDENTICAL to the best measured kernel
// (R10/R12/R14: 2507/2508/2497us). Known-regressing variants (do not revisit):
//   - CSIZE=16: comm blows up ~quadratically (R7, 3.5x)
//   - divergent per-lane spin: scheduler replay storm (R8, 3x)
//   - hand-packed f32x2 distance math: wrong (R2) or slower (R11, +8%)
//   - fusing gather work into the loop: any per-warp extra work adds directly
//     to the all-to-all critical path (R15, +16%)
//
// Per-point distance arithmetic is the VERBATIM scalar expression from the
// rel_err==0.0 kernels — do not touch.
//
// ONE-STAGE all-to-all reduction per iteration:
//   thread:  pairwise argmax tree over 16 points (prefer-left = lower index
//            on ties, exact jnp.argmax semantics)
//   warp:    2x REDUX -> warp key (held by EVERY lane)
//   all-to-all: lanes 0..7 each issue ONE remote store of the warp key to
//            rank=lane, slot [rank*NWARP+wid] (parallel fan-out)
//   every warp: CONVERGENT VOTED poll; lane L polls slot L (single vld64);
//            2x REDUX -> f.
// Keys: (dist_bits<<32) | (tag<<16) | (NN-1-idx); within one iteration all
// tags are equal so u64 max == (max dist, then first index) — jnp.argmax
// tie-breaking. Tags self-synchronize the spin; double buffering (j&1)
// prevents overwrite races: a warp writes buffer (j+2)&1 only after passing
// poll j+1, which required every warp of every rank to have posted j+1,
// which required them to have finished reading buffer j&1.
// ---------------------------------------------------------------------------
extern "C" __global__ void __launch_bounds__(T, 1) __cluster_dims__(CSIZE, 1, 1)
fps_kernel(const float* __restrict__ xyz)
{
    const int blk  = blockIdx.x;
    const int b    = blk / CSIZE;
    const u32 rank = (u32)(blk % CSIZE);
    const int tid  = threadIdx.x;
    const int wid  = tid >> 5;
    const int lane = tid & 31;

    extern __shared__ float smem[];
    float2* sxy = (float2*)smem;                    // [NN]  (128 KB)
    float*  sz  = smem + 2 * NN;                    // [NN]  (64 KB)
    u64* crossSlots = (u64*)(smem + 3 * NN);        // [2][NSLOT]

    const float* __restrict__ p = xyz + (size_t)b * NN * 3;

    // Full xyz table in smem (centroid lookup must cover all 16384 points)
    for (int i = tid; i < NN; i += T) {
        float x = p[3 * i + 0];
        float y = p[3 * i + 1];
        float z = p[3 * i + 2];
        sxy[i] = make_float2(x, y);
        sz[i]  = z;
    }
    if (tid < 2 * NSLOT) crossSlots[tid] = 0ull;
    __syncthreads();
    // all CTAs' slots must be zeroed before any peer's first DSMEM store
    asm volatile("barrier.cluster.arrive.aligned;" ::: "memory");
    asm volatile("barrier.cluster.wait.aligned;"   ::: "memory");

    // Own 16 points, register-resident: i_k = base + k*T (k asc => index asc)
    const int base = (int)rank * NC + tid;
    float X[PPT], Y[PPT], Z[PPT], D[PPT];
#pragma unroll
    for (int k = 0; k < PPT; k++) {
        const int i = base + k * T;
        float2 xy = sxy[i];
        X[k] = xy.x; Y[k] = xy.y; Z[k] = sz[i];
        D[k] = 1e10f;
    }

    const u32 csBase = smem_u32(crossSlots);

    // Per-lane peer address: lanes 0..7 target rank=lane, slot [rank*NWARP+wid].
    const u32 peerAddr = mapa_rank(csBase, (u32)(lane & (CSIZE - 1)))
                       + (u32)(((int)rank * NWARP + wid) * 8);

    // Lane L polls slot L (32 slots <-> 32 lanes).
    const u32 pollAddr = csBase + (u32)(lane * 8);

    int f = 0;   // init_far = 0 (reference)
    int* __restrict__ idxo = g_idx + b * NPOINT;

    for (int j = 0; j < NPOINT; j++) {
        const u32 tag = (u32)(j + 1);   // 1..8192 (14 bits)
        const u32 bufOff = (u32)((j & 1) * (NSLOT * 8));

        if (rank == 0 && tid == 0) idxo[j] = f;  // scan emits farthest BEFORE update

        // distance update — IDENTICAL source expression to prior passing rounds
        const float2 cxy = sxy[f];
        const float cz = sz[f];
        const float cx = cxy.x, cy = cxy.y;
        float nd[PPT];
#pragma unroll
        for (int k = 0; k < PPT; k++) {
            float dx = X[k] - cx;
            float dy = Y[k] - cy;
            float dz = Z[k] - cz;
            float d = dx * dx + dy * dy + dz * dz;
            float v = fminf(D[k], d);
            D[k] = v;
            nd[k] = v;
        }

        // thread-level argmax tree over 16 values; prefer-left keeps lowest k
        // (k ascending == global index ascending): first-index tie-break.
        float bd[PPT]; int bk[PPT];
#pragma unroll
        for (int k = 0; k < PPT; k++) { bd[k] = nd[k]; bk[k] = k; }
#pragma unroll
        for (int s = PPT / 2; s > 0; s >>= 1) {
#pragma unroll
            for (int k = 0; k < PPT; k++) {
                if (k < s) {
                    if (bd[k + s] > bd[k]) { bd[k] = bd[k + s]; bk[k] = bk[k + s]; }
                }
            }
        }
        const float best = bd[0];
        const int   bi   = base + bk[0] * T;

        // warp-level: max dist bits, then max of (NN-1-idx) among maxima
        const u32 ub  = __float_as_uint(best);          // dist >= 0: bit order == float order
        const u32 wm  = __reduce_max_sync(0xFFFFFFFFu, ub);
        const u32 cnd = (ub == wm) ? (u32)(NN - 1 - bi) : 0u;
        const u32 wi  = __reduce_max_sync(0xFFFFFFFFu, cnd);

        // all-to-all: lanes 0..7 each fire ONE remote store (parallel fan-out)
        const u64 wkey = ((u64)wm << 32) | ((u64)tag << 16) | (u64)wi;
        if (lane < CSIZE)
            st_cluster64(peerAddr + bufOff, wkey);

        // every warp: CONVERGENT voted poll, one slot per lane
        u64 k;
        do {
            k = vld64(pollAddr + bufOff);
        } while (__any_sync(0xFFFFFFFFu, (((u32)k >> 16) ^ tag) != 0u));

        const u32 hi = (u32)(k >> 32);
        const u32 lo = (u32)k;
        const u32 M1 = __reduce_max_sync(0xFFFFFFFFu, hi);
        const u32 C1 = (hi == M1) ? lo : 0u;  // tag bits identical across lanes
        const u32 M2 = __reduce_max_sync(0xFFFFFFFFu, C1);
        f = NN - 1 - (int)(M2 & 0x3FFFu);
    }
}

// ---------------------------------------------------------------------------
// L1-locality gather, two rows per block (R16). Blocks 0..B*C/2-1: one
// 1024-thread block handles feats rows (b,c) and (b,c+64) — each idx[m] load
// feeds TWO gathers (halves idx traffic, doubles useful MLP per issued
// index load); 2x64KB row footprint still fits L1 (228KB).
// Blocks B*C/2..B*C/2+B-1: xyz gather (one block per batch).
// ---------------------------------------------------------------------------
extern "C" __global__ void __launch_bounds__(GT)
gather_all_kernel(const float* __restrict__ feats,
                  const float* __restrict__ xyz,
                  float* __restrict__ out_feats,
                  float* __restrict__ out_xyz) {
    const int blk = blockIdx.x;
    const int tid = threadIdx.x;

    if (blk < BB * HCC) {
        const int b = blk / HCC;
        const int c = blk % HCC;                    // rows c and c+HCC
        const size_t r0 = (size_t)b * CC + c;
        const float* __restrict__ row0 = feats + r0 * NN;
        const float* __restrict__ row1 = feats + (r0 + HCC) * NN;
        float* __restrict__ dst0 = out_feats + r0 * NPOINT;
        float* __restrict__ dst1 = out_feats + (r0 + HCC) * NPOINT;
        const int* __restrict__ idx = g_idx + b * NPOINT;
#pragma unroll
        for (int q = 0; q < NPOINT / GT; q++) {
            const int m = tid + q * GT;
            const int i = idx[m];
            dst0[m] = row0[i];
            dst1[m] = row1[i];
        }
    } else {
        const int b = blk - BB * HCC;
        if (b >= BB) return;
        const int* __restrict__ idx = g_idx + b * NPOINT;
        const float* __restrict__ src = xyz + (size_t)b * NN * 3;
        float* __restrict__ dst = out_xyz + (size_t)b * NPOINT * 3;
        for (int m = tid; m < NPOINT; m += GT) {
            const int i = idx[m];
            dst[m * 3 + 0] = src[i * 3 + 0];
            dst[m * 3 + 1] = src[i * 3 + 1];
            dst[m * 3 + 2] = src[i * 3 + 2];
        }
    }
}

// ---------------------------------------------------------------------------
extern "C" void kernel_launch(void* const* d_in, const int* in_sizes, int n_in,
                              void* d_out, int out_size) {
    // Identify inputs by element count (robust to ordering):
    // feats = 8*128*16384 = 16777216, xyz = 8*16384*3 = 393216
    const float* feats = (const float*)d_in[0];
    const float* xyz   = (const float*)d_in[1];
    if (in_sizes[0] == BB * NN * 3) {
        xyz   = (const float*)d_in[0];
        feats = (const float*)d_in[1];
    }

    float* out = (float*)d_out;
    float* out_feats = out;                                   // B*C*NPOINT
    float* out_xyz   = out + (size_t)BB * CC * NPOINT;        // B*NPOINT*3

    const size_t smem = (size_t)3 * NN * sizeof(float)
                      + 2 * NSLOT * sizeof(u64);
    cudaFuncSetAttribute(fps_kernel,
                         cudaFuncAttributeMaxDynamicSharedMemorySize,
                         (int)smem);

    fps_kernel<<<BB * CSIZE, T, smem>>>(xyz);

    gather_all_kernel<<<BB * HCC + BB, GT>>>(feats, xyz, out_feats, out_xyz);
}